// round 15
// baseline (speedup 1.0000x reference)
#include <cuda_runtime.h>
#include <cuda_fp16.h>
#include <cstdint>
#include <math.h>

#define D_DIM 2048
#define B_TOK 4096

// ---------------- scratch (device globals; no allocation allowed) ----------
__device__ __half g_srcRh[(size_t)B_TOK * D_DIM];
__device__ __half g_srcTh[(size_t)B_TOK * D_DIM];
__device__ __half g_thkRh[(size_t)D_DIM * D_DIM];
__device__ __half g_thkTh[(size_t)D_DIM * D_DIM];
__device__ __half g_WRh [(size_t)D_DIM * D_DIM];
__device__ __half g_thqTh[(size_t)D_DIM * D_DIM];
__device__ __half g_qvh [(size_t)B_TOK * D_DIM];
__device__ __half g_Sh  [(size_t)D_DIM * D_DIM];
__device__ float  g_M   [(size_t)D_DIM * D_DIM];
__device__ __half g_MTh [(size_t)D_DIM * D_DIM];
__device__ __half g_T1Th[(size_t)D_DIM * D_DIM];
__device__ __half g_Wnh [(size_t)D_DIM * D_DIM];
__device__ float  g_part[32 * D_DIM];
__device__ float  g_c   [D_DIM];
__device__ float  g_v   [D_DIM];
__device__ float  g_bn  [D_DIM];

// ---------------- PTX helpers ----------------------------------------------
__device__ __forceinline__ void cp16(uint32_t dst, const void* src) {
    asm volatile("cp.async.cg.shared.global [%0], [%1], 16;" :: "r"(dst), "l"(src));
}

__device__ __forceinline__ void ldsm4(uint32_t& r0, uint32_t& r1, uint32_t& r2, uint32_t& r3,
                                      uint32_t addr) {
    asm volatile("ldmatrix.sync.aligned.m8n8.x4.shared.b16 {%0,%1,%2,%3}, [%4];"
                 : "=r"(r0), "=r"(r1), "=r"(r2), "=r"(r3) : "r"(addr));
}

__device__ __forceinline__ void mma_f16(float c[4], const uint32_t a[4],
                                        uint32_t b0, uint32_t b1) {
    asm volatile(
        "mma.sync.aligned.m16n8k16.row.col.f32.f16.f16.f32 "
        "{%0,%1,%2,%3}, {%4,%5,%6,%7}, {%8,%9}, {%0,%1,%2,%3};"
        : "+f"(c[0]), "+f"(c[1]), "+f"(c[2]), "+f"(c[3])
        : "r"(a[0]), "r"(a[1]), "r"(a[2]), "r"(a[3]), "r"(b0), "r"(b1));
}

__device__ __forceinline__ void mma_f16h(uint32_t c[2], const uint32_t a[4],
                                         uint32_t b0, uint32_t b1) {
    asm volatile(
        "mma.sync.aligned.m16n8k16.row.col.f16.f16.f16.f16 "
        "{%0,%1}, {%2,%3,%4,%5}, {%6,%7}, {%0,%1};"
        : "+r"(c[0]), "+r"(c[1])
        : "r"(a[0]), "r"(a[1]), "r"(a[2]), "r"(a[3]), "r"(b0), "r"(b1));
}

// ---------------------------------------------------------------------------
// fp16 4-warp NT GEMM: C[M,N] = A[M,K]*B[N,K]^T.
// CTA 128x128, 4 warps of 64x64, BK=64 halves.
// ACC 0: fp32 accumulate, 3-stage pipeline (96KB), occ 2  (first-order path)
// ACC 1: fp16 accumulate, 2-stage pipeline (64KB), occ 3  (gradient path)
// EPI 0: v = acc
// EPI 1: v = acc + e1[idx] - e2[idx]
// EPI 2: v = e1[idx] - e2[idx]*coef*(acc + ev0[r]*ev1[c])
// EPI 5: v = acc + half(e1h[idx]) + ev0[col]
// MODE 0: fp32 C.  MODE 1: half CT only.  MODE 2: fp32 C + half CT.
// MODE 3: half Ch (non-transposed).
// ---------------------------------------------------------------------------
template <int EPI, int MODE, int ACC>
__global__ void __launch_bounds__(128, (ACC == 1) ? 3 : 2)
hgemm(const __half* __restrict__ A, const __half* __restrict__ B,
      float* __restrict__ C, __half* __restrict__ Ch, __half* __restrict__ CTh,
      int M, int N, int K,
      const float* __restrict__ e1, const float* __restrict__ e2,
      const float* __restrict__ ev0, const float* __restrict__ ev1,
      const __half* __restrict__ e1h, float coef)
{
    constexpr int BK   = 64;             // halves
    constexpr int TILE = 128 * 128;      // bytes
    constexpr int SS   = 2 * TILE;
    constexpr int NST  = (ACC == 1) ? 2 : 3;

    extern __shared__ __align__(128) char smraw[];
    const uint32_t sb = (uint32_t)__cvta_generic_to_shared(smraw);

    const int tid  = threadIdx.x;
    const int lane = tid & 31;
    const int wid  = tid >> 5;
    const int wm   = (wid & 1) * 64;
    const int wn   = (wid >> 1) * 64;
    const int m0   = blockIdx.y * 128;
    const int n0   = blockIdx.x * 128;

    const int lr = tid >> 3;
    const int lc = tid & 7;
    const uint32_t lOff = (uint32_t)(lr * 128 + ((lc ^ (lr & 7)) << 4));
    const __half* aG = A + (size_t)(m0 + lr) * K + lc * 8;
    const __half* bG = B + (size_t)(n0 + lr) * K + lc * 8;

    auto loadTile = [&](int t) {
        const uint32_t base = sb + (uint32_t)((t % NST) * SS);
        const __half* a = aG + (size_t)t * BK;
        const __half* b = bG + (size_t)t * BK;
#pragma unroll
        for (int i = 0; i < 8; ++i)
            cp16(base + lOff + 2048u * i, a + (size_t)(16 * i) * K);
#pragma unroll
        for (int i = 0; i < 8; ++i)
            cp16(base + TILE + lOff + 2048u * i, b + (size_t)(16 * i) * K);
        asm volatile("cp.async.commit_group;" ::: "memory");
    };

    const int rr  = lane & 7;
    const int loA = (lane >> 3) & 1;
    const int hiA = (lane >> 4) & 1;
    const int loB = (lane >> 4) & 1;
    const int hiB = (lane >> 3) & 1;
    const uint32_t swz = (uint32_t)rr << 4;

    uint32_t aRow[4], bRow[4];
#pragma unroll
    for (int mf = 0; mf < 4; ++mf)
        aRow[mf] = (uint32_t)((wm + mf * 16 + loA * 8 + rr) * 128);
#pragma unroll
    for (int nfp = 0; nfp < 4; ++nfp)
        bRow[nfp] = (uint32_t)((wn + nfp * 16 + loB * 8 + rr) * 128);

    float    accf[4][8][4];
    uint32_t acch[4][8][2];
    if (ACC == 0) {
#pragma unroll
        for (int i = 0; i < 4; ++i)
#pragma unroll
            for (int j = 0; j < 8; ++j)
#pragma unroll
                for (int k = 0; k < 4; ++k) accf[i][j][k] = 0.0f;
    } else {
#pragma unroll
        for (int i = 0; i < 4; ++i)
#pragma unroll
            for (int j = 0; j < 8; ++j) { acch[i][j][0] = 0u; acch[i][j][1] = 0u; }
    }

    const int nt = K / BK;
    loadTile(0);
    loadTile(1);

    for (int t = 0; t < nt; ++t) {
        if (t + 1 < nt) asm volatile("cp.async.wait_group 1;" ::: "memory");
        else            asm volatile("cp.async.wait_group 0;" ::: "memory");
        __syncthreads();
        if (ACC == 0 && t + 2 < nt) loadTile(t + 2);   // 3-stage: safe (stage t-1)

        const uint32_t stA = sb + (uint32_t)((t % NST) * SS);
        const uint32_t stB = stA + TILE;

#pragma unroll
        for (int kk = 0; kk < 4; ++kk) {
            const uint32_t ak = (((uint32_t)(2 * kk + hiA)) << 4) ^ swz;
            const uint32_t bk = (((uint32_t)(2 * kk + hiB)) << 4) ^ swz;
            uint32_t af[4][4];
#pragma unroll
            for (int mf = 0; mf < 4; ++mf)
                ldsm4(af[mf][0], af[mf][1], af[mf][2], af[mf][3], stA + aRow[mf] + ak);
            uint32_t bf[4][4];
#pragma unroll
            for (int nfp = 0; nfp < 4; ++nfp)
                ldsm4(bf[nfp][0], bf[nfp][1], bf[nfp][2], bf[nfp][3], stB + bRow[nfp] + bk);
#pragma unroll
            for (int mf = 0; mf < 4; ++mf)
#pragma unroll
                for (int nf = 0; nf < 8; ++nf) {
                    if (ACC == 0)
                        mma_f16(accf[mf][nf], af[mf],
                                bf[nf >> 1][(nf & 1) * 2], bf[nf >> 1][(nf & 1) * 2 + 1]);
                    else
                        mma_f16h(acch[mf][nf], af[mf],
                                 bf[nf >> 1][(nf & 1) * 2], bf[nf >> 1][(nf & 1) * 2 + 1]);
                }
        }

        if (ACC == 1) {   // 2-stage: load t+2 only after ALL warps consumed tile t
            __syncthreads();
            if (t + 2 < nt) loadTile(t + 2);
        }
    }

    const int g   = lane >> 2;
    const int tig = lane & 3;
    __half* hsm = reinterpret_cast<__half*>(smraw);
    if (MODE == 1 || MODE == 2) __syncthreads();

#pragma unroll
    for (int mf = 0; mf < 4; ++mf) {
#pragma unroll
        for (int nf = 0; nf < 8; ++nf) {
#pragma unroll
            for (int h = 0; h < 2; ++h) {
                const int rl = wm + mf * 16 + g + h * 8;
                const int cl = wn + nf * 8 + 2 * tig;
                const int r = m0 + rl;
                const int c = n0 + cl;
                const size_t idx = (size_t)r * N + c;
                float v0, v1;
                if (ACC == 0) {
                    v0 = accf[mf][nf][h * 2 + 0];
                    v1 = accf[mf][nf][h * 2 + 1];
                } else {
                    uint32_t p = acch[mf][nf][h];
                    __half2 hp = *reinterpret_cast<__half2*>(&p);
                    v0 = __half2float(hp.x);
                    v1 = __half2float(hp.y);
                }
                if (EPI == 1) {
                    const float2 a1 = *reinterpret_cast<const float2*>(e1 + idx);
                    const float2 a2 = *reinterpret_cast<const float2*>(e2 + idx);
                    v0 += a1.x - a2.x;
                    v1 += a1.y - a2.y;
                } else if (EPI == 2) {
                    const float2 w  = *reinterpret_cast<const float2*>(e1 + idx);
                    const float2 lr = *reinterpret_cast<const float2*>(e2 + idx);
                    const float bi  = ev0[r];
                    v0 = w.x - lr.x * (coef * (v0 + bi * ev1[c]));
                    v1 = w.y - lr.y * (coef * (v1 + bi * ev1[c + 1]));
                } else if (EPI == 5) {
                    const __half2 qh = *reinterpret_cast<const __half2*>(e1h + idx);
                    v0 += __half2float(qh.x) + ev0[c];
                    v1 += __half2float(qh.y) + ev0[c + 1];
                }
                if (MODE == 0 || MODE == 2) {
                    float2 out; out.x = v0; out.y = v1;
                    *reinterpret_cast<float2*>(C + idx) = out;
                }
                if (MODE == 3) {
                    __half2 hp;
                    hp.x = __float2half_rn(v0);
                    hp.y = __float2half_rn(v1);
                    *reinterpret_cast<__half2*>(Ch + idx) = hp;
                }
                if (MODE == 1 || MODE == 2) {
                    hsm[(cl + 0) * 136 + rl] = __float2half_rn(v0);
                    hsm[(cl + 1) * 136 + rl] = __float2half_rn(v1);
                }
            }
        }
    }

    if (MODE == 1 || MODE == 2) {
        __syncthreads();
#pragma unroll
        for (int i = 0; i < 16; ++i) {
            const int chunk = tid + (i << 7);
            const int row  = chunk >> 4;
            const int c16  = (chunk & 15) << 3;
            const uint4 v = *reinterpret_cast<const uint4*>(hsm + row * 136 + c16);
            *reinterpret_cast<uint4*>(CTh + (size_t)(n0 + row) * M + m0 + c16) = v;
        }
    }
}

// ---------------------------------------------------------------------------
// fp16 symmetric Gram GEMM: fp16 accumulate, 2-stage, occ 3.
// ---------------------------------------------------------------------------
__global__ void __launch_bounds__(128, 3)
symgemmH(const __half* __restrict__ A, __half* __restrict__ Ch, int N, int K)
{
    constexpr int BK   = 64;
    constexpr int TILE = 128 * 128;
    constexpr int SS   = 2 * TILE;

    extern __shared__ __align__(128) char smraw[];
    const uint32_t sb = (uint32_t)__cvta_generic_to_shared(smraw);

    const int tid  = threadIdx.x;
    const int lane = tid & 31;
    const int wid  = tid >> 5;
    const int wm   = (wid & 1) * 64;
    const int wn   = (wid >> 1) * 64;

    const int i = blockIdx.x;
    int e = (int)((sqrtf(8.0f * (float)i + 1.0f) - 1.0f) * 0.5f);
    while ((e + 1) * (e + 2) / 2 <= i) ++e;
    while (e * (e + 1) / 2 > i) --e;
    const int by = e;
    const int bx = i - e * (e + 1) / 2;
    const int m0 = by * 128;
    const int n0 = bx * 128;

    const int lr = tid >> 3;
    const int lc = tid & 7;
    const uint32_t lOff = (uint32_t)(lr * 128 + ((lc ^ (lr & 7)) << 4));
    const __half* aG = A + (size_t)(m0 + lr) * K + lc * 8;
    const __half* bG = A + (size_t)(n0 + lr) * K + lc * 8;

    auto loadTile = [&](int t) {
        const uint32_t base = sb + (uint32_t)((t & 1) * SS);
        const __half* a = aG + (size_t)t * BK;
        const __half* b = bG + (size_t)t * BK;
#pragma unroll
        for (int ii = 0; ii < 8; ++ii)
            cp16(base + lOff + 2048u * ii, a + (size_t)(16 * ii) * K);
#pragma unroll
        for (int ii = 0; ii < 8; ++ii)
            cp16(base + TILE + lOff + 2048u * ii, b + (size_t)(16 * ii) * K);
        asm volatile("cp.async.commit_group;" ::: "memory");
    };

    const int rr  = lane & 7;
    const int loA = (lane >> 3) & 1;
    const int hiA = (lane >> 4) & 1;
    const int loB = (lane >> 4) & 1;
    const int hiB = (lane >> 3) & 1;
    const uint32_t swz = (uint32_t)rr << 4;

    uint32_t aRow[4], bRow[4];
#pragma unroll
    for (int mf = 0; mf < 4; ++mf)
        aRow[mf] = (uint32_t)((wm + mf * 16 + loA * 8 + rr) * 128);
#pragma unroll
    for (int nfp = 0; nfp < 4; ++nfp)
        bRow[nfp] = (uint32_t)((wn + nfp * 16 + loB * 8 + rr) * 128);

    uint32_t acch[4][8][2];
#pragma unroll
    for (int a = 0; a < 4; ++a)
#pragma unroll
        for (int b = 0; b < 8; ++b) { acch[a][b][0] = 0u; acch[a][b][1] = 0u; }

    const int nt = K / BK;
    loadTile(0);
    loadTile(1);

    for (int t = 0; t < nt; ++t) {
        if (t + 1 < nt) asm volatile("cp.async.wait_group 1;" ::: "memory");
        else            asm volatile("cp.async.wait_group 0;" ::: "memory");
        __syncthreads();

        const uint32_t stA = sb + (uint32_t)((t & 1) * SS);
        const uint32_t stB = stA + TILE;

#pragma unroll
        for (int kk = 0; kk < 4; ++kk) {
            const uint32_t ak = (((uint32_t)(2 * kk + hiA)) << 4) ^ swz;
            const uint32_t bk = (((uint32_t)(2 * kk + hiB)) << 4) ^ swz;
            uint32_t af[4][4];
#pragma unroll
            for (int mf = 0; mf < 4; ++mf)
                ldsm4(af[mf][0], af[mf][1], af[mf][2], af[mf][3], stA + aRow[mf] + ak);
            uint32_t bf[4][4];
#pragma unroll
            for (int nfp = 0; nfp < 4; ++nfp)
                ldsm4(bf[nfp][0], bf[nfp][1], bf[nfp][2], bf[nfp][3], stB + bRow[nfp] + bk);
#pragma unroll
            for (int mf = 0; mf < 4; ++mf)
#pragma unroll
                for (int nf = 0; nf < 8; ++nf)
                    mma_f16h(acch[mf][nf], af[mf],
                             bf[nf >> 1][(nf & 1) * 2], bf[nf >> 1][(nf & 1) * 2 + 1]);
        }

        __syncthreads();
        if (t + 2 < nt) loadTile(t + 2);
    }

    const int g   = lane >> 2;
    const int tig = lane & 3;
    __half* hsm = reinterpret_cast<__half*>(smraw);
    const bool mirror = (bx != by);
    if (mirror) __syncthreads();

#pragma unroll
    for (int mf = 0; mf < 4; ++mf) {
#pragma unroll
        for (int nf = 0; nf < 8; ++nf) {
#pragma unroll
            for (int h = 0; h < 2; ++h) {
                const int rl = wm + mf * 16 + g + h * 8;
                const int cl = wn + nf * 8 + 2 * tig;
                uint32_t p = acch[mf][nf][h];
                __half2 hp = *reinterpret_cast<__half2*>(&p);
                *reinterpret_cast<__half2*>(Ch + (size_t)(m0 + rl) * N + n0 + cl) = hp;
                if (mirror) {
                    hsm[(cl + 0) * 136 + rl] = hp.x;
                    hsm[(cl + 1) * 136 + rl] = hp.y;
                }
            }
        }
    }

    if (mirror) {
        __syncthreads();
#pragma unroll
        for (int ii = 0; ii < 16; ++ii) {
            const int chunk = tid + (ii << 7);
            const int row  = chunk >> 4;
            const int c16  = (chunk & 15) << 3;
            const uint4 v = *reinterpret_cast<const uint4*>(hsm + row * 136 + c16);
            *reinterpret_cast<uint4*>(Ch + (size_t)(n0 + row) * N + m0 + c16) = v;
        }
    }
}

// ---------------- small kernels ----------------------------------------------
__global__ void half_kernel(const float* __restrict__ in, __half* __restrict__ out, int n)
{
    int i = blockIdx.x * blockDim.x + threadIdx.x;
    if (i < n) out[i] = __float2half_rn(in[i]);
}

__global__ void prep_dual(const float* __restrict__ in, __half* __restrict__ outRh,
                          __half* __restrict__ outTh, int R, int C)
{
    __shared__ float tile[32][33];
    const int bx = blockIdx.x * 32, by = blockIdx.y * 32;
    const int x = threadIdx.x, y = threadIdx.y;
#pragma unroll
    for (int j = 0; j < 32; j += 8) {
        const float v = in[(size_t)(by + y + j) * C + bx + x];
        tile[y + j][x] = v;
        outRh[(size_t)(by + y + j) * C + bx + x] = __float2half_rn(v);
    }
    __syncthreads();
#pragma unroll
    for (int j = 0; j < 32; j += 8)
        outTh[(size_t)(bx + y + j) * R + by + x] = __float2half_rn(tile[x][y + j]);
}

__global__ void prep_T(const float* __restrict__ in, __half* __restrict__ outTh, int R, int C)
{
    __shared__ float tile[32][33];
    const int bx = blockIdx.x * 32, by = blockIdx.y * 32;
    const int x = threadIdx.x, y = threadIdx.y;
#pragma unroll
    for (int j = 0; j < 32; j += 8)
        tile[y + j][x] = in[(size_t)(by + y + j) * C + bx + x];
    __syncthreads();
#pragma unroll
    for (int j = 0; j < 32; j += 8)
        outTh[(size_t)(bx + y + j) * R + by + x] = __float2half_rn(tile[x][y + j]);
}

__global__ void colsum_kernel(const float* __restrict__ in, float* __restrict__ part)
{
    int col = blockIdx.x * blockDim.x + threadIdx.x;
    int chunk = blockIdx.y;
    const float* p = in + (size_t)chunk * 128 * D_DIM + col;
    float s0 = 0.f, s1 = 0.f, s2 = 0.f, s3 = 0.f;
#pragma unroll
    for (int r = 0; r < 128; r += 4) {
        s0 += p[(size_t)(r + 0) * D_DIM];
        s1 += p[(size_t)(r + 1) * D_DIM];
        s2 += p[(size_t)(r + 2) * D_DIM];
        s3 += p[(size_t)(r + 3) * D_DIM];
    }
    part[chunk * D_DIM + col] = (s0 + s1) + (s2 + s3);
}

__global__ void creduce_kernel(const float* __restrict__ part, float* __restrict__ c)
{
    int j = blockIdx.x * blockDim.x + threadIdx.x;
    float s = 0.f;
#pragma unroll
    for (int ch = 0; ch < 32; ++ch) s += part[ch * D_DIM + j];
    c[j] = s;
}

__global__ void vecmat_kernel(const float* __restrict__ vec, const float* __restrict__ Mat,
                              float* __restrict__ outv)
{
    int j = blockIdx.x * blockDim.x + threadIdx.x;
    float s0 = 0.f, s1 = 0.f, s2 = 0.f, s3 = 0.f;
#pragma unroll 4
    for (int k = 0; k < D_DIM; k += 4) {
        s0 += vec[k + 0] * Mat[(size_t)(k + 0) * D_DIM + j];
        s1 += vec[k + 1] * Mat[(size_t)(k + 1) * D_DIM + j];
        s2 += vec[k + 2] * Mat[(size_t)(k + 2) * D_DIM + j];
        s3 += vec[k + 3] * Mat[(size_t)(k + 3) * D_DIM + j];
    }
    outv[j] = (s0 + s1) + (s2 + s3);
}

__global__ void bn_kernel(const float* __restrict__ Mm, const float* __restrict__ c,
                          const float* __restrict__ b, const float* __restrict__ lrb,
                          float* __restrict__ bn, float coef)
{
    int j = blockIdx.x * blockDim.x + threadIdx.x;
    float s0 = 0.f, s1 = 0.f, s2 = 0.f, s3 = 0.f;
#pragma unroll 4
    for (int k = 0; k < D_DIM; k += 4) {
        s0 += c[k + 0] * Mm[(size_t)(k + 0) * D_DIM + j];
        s1 += c[k + 1] * Mm[(size_t)(k + 1) * D_DIM + j];
        s2 += c[k + 2] * Mm[(size_t)(k + 2) * D_DIM + j];
        s3 += c[k + 3] * Mm[(size_t)(k + 3) * D_DIM + j];
    }
    float s = (s0 + s1) + (s2 + s3);
    bn[j] = b[j] - lrb[j] * coef * (s + (float)B_TOK * b[j]);
}

// ---------------- host --------------------------------------------------------
extern "C" void kernel_launch(void* const* d_in, const int* in_sizes, int n_in,
                              void* d_out, int out_size)
{
    const float* src  = (const float*)d_in[0];
    const float* th_k = (const float*)d_in[1];
    const float* th_q = (const float*)d_in[2];
    const float* th_v = (const float*)d_in[3];
    const float* W    = (const float*)d_in[4];
    const float* b    = (const float*)d_in[5];
    const float* lr_w = (const float*)d_in[6];
    const float* lr_b = (const float*)d_in[7];
    float* out = (float*)d_out;

    float *Mm, *part, *cvec, *vvec, *bn;
    __half *srcRh, *srcTh, *thkRh, *thkTh, *WRh, *thqTh, *qvh, *Sh, *MTh, *T1Th, *Wnh;
    cudaGetSymbolAddress((void**)&srcRh, g_srcRh);
    cudaGetSymbolAddress((void**)&srcTh, g_srcTh);
    cudaGetSymbolAddress((void**)&thkRh, g_thkRh);
    cudaGetSymbolAddress((void**)&thkTh, g_thkTh);
    cudaGetSymbolAddress((void**)&WRh,   g_WRh);
    cudaGetSymbolAddress((void**)&thqTh, g_thqTh);
    cudaGetSymbolAddress((void**)&qvh,   g_qvh);
    cudaGetSymbolAddress((void**)&Sh,    g_Sh);
    cudaGetSymbolAddress((void**)&Mm,    g_M);
    cudaGetSymbolAddress((void**)&MTh,   g_MTh);
    cudaGetSymbolAddress((void**)&T1Th,  g_T1Th);
    cudaGetSymbolAddress((void**)&Wnh,   g_Wnh);
    cudaGetSymbolAddress((void**)&part,  g_part);
    cudaGetSymbolAddress((void**)&cvec,  g_c);
    cudaGetSymbolAddress((void**)&vvec,  g_v);
    cudaGetSymbolAddress((void**)&bn,    g_bn);

    static cudaStream_t s2 = nullptr;
    static cudaEvent_t evFork = nullptr, evJoin = nullptr;
    if (s2 == nullptr) {
        cudaStreamCreateWithFlags(&s2, cudaStreamNonBlocking);
        cudaEventCreateWithFlags(&evFork, cudaEventDisableTiming);
        cudaEventCreateWithFlags(&evJoin, cudaEventDisableTiming);
    }

    const float coef = 2.0f / ((float)B_TOK * (float)D_DIM);
    const int SM3 = 3 * 2 * 128 * 128;   // 98304 (ACC 0)
    const int SM2 = 2 * 2 * 128 * 128;   // 65536 (ACC 1)

    cudaFuncSetAttribute(hgemm<1, 2, 1>, cudaFuncAttributeMaxDynamicSharedMemorySize, SM2);
    cudaFuncSetAttribute(hgemm<0, 1, 1>, cudaFuncAttributeMaxDynamicSharedMemorySize, SM2);
    cudaFuncSetAttribute(hgemm<2, 3, 1>, cudaFuncAttributeMaxDynamicSharedMemorySize, SM2);
    cudaFuncSetAttribute(hgemm<0, 3, 0>, cudaFuncAttributeMaxDynamicSharedMemorySize, SM3);
    cudaFuncSetAttribute(hgemm<5, 0, 0>, cudaFuncAttributeMaxDynamicSharedMemorySize, SM3);
    cudaFuncSetAttribute(symgemmH,       cudaFuncAttributeMaxDynamicSharedMemorySize, SM2);

    dim3 tb(32, 8);
    dim3 gridD(D_DIM / 128, D_DIM / 128);   // 256 CTAs
    dim3 gridB(D_DIM / 128, B_TOK / 128);   // 512 CTAs
    const int nSymTiles = (D_DIM / 128) * (D_DIM / 128 + 1) / 2;   // 136

    // ---- prep (main) ----
    prep_dual<<<dim3(D_DIM / 32, B_TOK / 32), tb>>>(src, srcRh, srcTh, B_TOK, D_DIM);
    prep_dual<<<dim3(D_DIM / 32, D_DIM / 32), tb>>>(th_k, thkRh, thkTh, D_DIM, D_DIM);

    // ---- fork: W half, M-GEMM, theta_q^T, qv = src @ theta_q ----
    cudaEventRecord(evFork, 0);
    cudaStreamWaitEvent(s2, evFork, 0);
    half_kernel<<<(D_DIM * D_DIM + 255) / 256, 256, 0, s2>>>(W, WRh, D_DIM * D_DIM);
    hgemm<1, 2, 1><<<gridD, 128, SM2, s2>>>(thkRh, WRh, Mm, nullptr, MTh, D_DIM, D_DIM, D_DIM,
                                            th_k, th_v, nullptr, nullptr, nullptr, 0.f);
    prep_T<<<dim3(D_DIM / 32, D_DIM / 32), tb, 0, s2>>>(th_q, thqTh, D_DIM, D_DIM);
    hgemm<0, 3, 0><<<gridB, 128, SM3, s2>>>(srcRh, thqTh, nullptr, qvh, nullptr,
                                            B_TOK, D_DIM, D_DIM,
                                            nullptr, nullptr, nullptr, nullptr, nullptr, 0.f);
    cudaEventRecord(evJoin, s2);

    // ---- main chain ----
    colsum_kernel<<<dim3(D_DIM / 256, 32), 256>>>(src, part);
    creduce_kernel<<<D_DIM / 256, 256>>>(part, cvec);
    vecmat_kernel<<<D_DIM / 128, 128>>>(cvec, th_k, vvec);
    symgemmH<<<nSymTiles, 128, SM2>>>(srcTh, Sh, D_DIM, B_TOK);

    // T1T = (S @ theta_k)^T
    hgemm<0, 1, 1><<<gridD, 128, SM2>>>(Sh, thkTh, nullptr, nullptr, T1Th, D_DIM, D_DIM, D_DIM,
                                        nullptr, nullptr, nullptr, nullptr, nullptr, 0.f);

    cudaStreamWaitEvent(0, evJoin, 0);

    bn_kernel<<<D_DIM / 128, 128>>>(Mm, cvec, b, lr_b, bn, coef);

    // Wnh = half( W - lr_w * coef * (M^T @ T1 + b (x) v) )
    hgemm<2, 3, 1><<<gridD, 128, SM2>>>(MTh, T1Th, nullptr, Wnh, nullptr, D_DIM, D_DIM, D_DIM,
                                        W, lr_w, b, vvec, nullptr, coef);

    // z = qv @ Wn^T + qv + bn   (fp32 out)
    hgemm<5, 0, 0><<<gridB, 128, SM3>>>(qvh, Wnh, out, nullptr, nullptr, B_TOK, D_DIM, D_DIM,
                                        nullptr, nullptr, bn, nullptr, qvh, 0.f);
}

// round 16
// speedup vs baseline: 1.0654x; 1.0654x over previous
#include <cuda_runtime.h>
#include <cuda_fp16.h>
#include <cstdint>
#include <math.h>

#define D_DIM 2048
#define B_TOK 4096

// ---------------- scratch (device globals; no allocation allowed) ----------
__device__ __half g_srcRh[(size_t)B_TOK * D_DIM];
__device__ __half g_srcTh[(size_t)B_TOK * D_DIM];
__device__ __half g_thkRh[(size_t)D_DIM * D_DIM];
__device__ __half g_thkTh[(size_t)D_DIM * D_DIM];
__device__ __half g_WRh [(size_t)D_DIM * D_DIM];
__device__ __half g_thqTh[(size_t)D_DIM * D_DIM];
__device__ __half g_qvh [(size_t)B_TOK * D_DIM];
__device__ __half g_Sh  [(size_t)D_DIM * D_DIM];
__device__ float  g_M   [(size_t)D_DIM * D_DIM];
__device__ __half g_MTh [(size_t)D_DIM * D_DIM];
__device__ __half g_T1Th[(size_t)D_DIM * D_DIM];
__device__ __half g_Wnh [(size_t)D_DIM * D_DIM];
__device__ float  g_part[32 * D_DIM];
__device__ float  g_c   [D_DIM];
__device__ float  g_v   [D_DIM];
__device__ float  g_bn  [D_DIM];

// ---------------- PTX helpers ----------------------------------------------
__device__ __forceinline__ void cp16(uint32_t dst, const void* src) {
    asm volatile("cp.async.cg.shared.global [%0], [%1], 16;" :: "r"(dst), "l"(src));
}

__device__ __forceinline__ void ldsm4(uint32_t& r0, uint32_t& r1, uint32_t& r2, uint32_t& r3,
                                      uint32_t addr) {
    asm volatile("ldmatrix.sync.aligned.m8n8.x4.shared.b16 {%0,%1,%2,%3}, [%4];"
                 : "=r"(r0), "=r"(r1), "=r"(r2), "=r"(r3) : "r"(addr));
}

__device__ __forceinline__ void mma_f16(float c[4], const uint32_t a[4],
                                        uint32_t b0, uint32_t b1) {
    asm volatile(
        "mma.sync.aligned.m16n8k16.row.col.f32.f16.f16.f32 "
        "{%0,%1,%2,%3}, {%4,%5,%6,%7}, {%8,%9}, {%0,%1,%2,%3};"
        : "+f"(c[0]), "+f"(c[1]), "+f"(c[2]), "+f"(c[3])
        : "r"(a[0]), "r"(a[1]), "r"(a[2]), "r"(a[3]), "r"(b0), "r"(b1));
}

// ---------------------------------------------------------------------------
// fp16 4-warp NT GEMM (R12/R14 proven): C[M,N] = A[M,K]*B[N,K]^T, fp32 acc.
// CTA 128x128, 4 warps of 64x64, BK=64 halves, 3-stage, launch_bounds(128,2).
// EPI 0: v = acc
// EPI 1: v = acc + e1[idx] - e2[idx]
// EPI 2: v = e1[idx] - e2[idx]*coef*(acc + ev0[r]*ev1[c])
// EPI 5: v = acc + half(e1h[idx]) + ev0[col]
// MODE 0: fp32 C.  MODE 1: half CT only.  MODE 2: fp32 C + half CT.
// MODE 3: half Ch (non-transposed).
// ---------------------------------------------------------------------------
template <int EPI, int MODE>
__global__ void __launch_bounds__(128, 2)
hgemm(const __half* __restrict__ A, const __half* __restrict__ B,
      float* __restrict__ C, __half* __restrict__ Ch, __half* __restrict__ CTh,
      int M, int N, int K,
      const float* __restrict__ e1, const float* __restrict__ e2,
      const float* __restrict__ ev0, const float* __restrict__ ev1,
      const __half* __restrict__ e1h, float coef)
{
    constexpr int BK   = 64;             // halves
    constexpr int TILE = 128 * 128;      // bytes
    constexpr int SS   = 2 * TILE;

    extern __shared__ __align__(128) char smraw[];
    const uint32_t sb = (uint32_t)__cvta_generic_to_shared(smraw);

    const int tid  = threadIdx.x;
    const int lane = tid & 31;
    const int wid  = tid >> 5;
    const int wm   = (wid & 1) * 64;
    const int wn   = (wid >> 1) * 64;
    const int m0   = blockIdx.y * 128;
    const int n0   = blockIdx.x * 128;

    const int lr = tid >> 3;
    const int lc = tid & 7;
    const uint32_t lOff = (uint32_t)(lr * 128 + ((lc ^ (lr & 7)) << 4));
    const __half* aG = A + (size_t)(m0 + lr) * K + lc * 8;
    const __half* bG = B + (size_t)(n0 + lr) * K + lc * 8;

    auto loadTile = [&](int t) {
        const uint32_t base = sb + (uint32_t)((t % 3) * SS);
        const __half* a = aG + (size_t)t * BK;
        const __half* b = bG + (size_t)t * BK;
#pragma unroll
        for (int i = 0; i < 8; ++i)
            cp16(base + lOff + 2048u * i, a + (size_t)(16 * i) * K);
#pragma unroll
        for (int i = 0; i < 8; ++i)
            cp16(base + TILE + lOff + 2048u * i, b + (size_t)(16 * i) * K);
        asm volatile("cp.async.commit_group;" ::: "memory");
    };

    const int rr  = lane & 7;
    const int loA = (lane >> 3) & 1;
    const int hiA = (lane >> 4) & 1;
    const int loB = (lane >> 4) & 1;
    const int hiB = (lane >> 3) & 1;
    const uint32_t swz = (uint32_t)rr << 4;

    uint32_t aRow[4], bRow[4];
#pragma unroll
    for (int mf = 0; mf < 4; ++mf)
        aRow[mf] = (uint32_t)((wm + mf * 16 + loA * 8 + rr) * 128);
#pragma unroll
    for (int nfp = 0; nfp < 4; ++nfp)
        bRow[nfp] = (uint32_t)((wn + nfp * 16 + loB * 8 + rr) * 128);

    float acc[4][8][4];
#pragma unroll
    for (int i = 0; i < 4; ++i)
#pragma unroll
        for (int j = 0; j < 8; ++j)
#pragma unroll
            for (int k = 0; k < 4; ++k) acc[i][j][k] = 0.0f;

    const int nt = K / BK;
    loadTile(0);
    loadTile(1);

    for (int t = 0; t < nt; ++t) {
        if (t + 1 < nt) asm volatile("cp.async.wait_group 1;" ::: "memory");
        else            asm volatile("cp.async.wait_group 0;" ::: "memory");
        __syncthreads();
        if (t + 2 < nt) loadTile(t + 2);

        const uint32_t stA = sb + (uint32_t)((t % 3) * SS);
        const uint32_t stB = stA + TILE;

#pragma unroll
        for (int kk = 0; kk < 4; ++kk) {
            const uint32_t ak = (((uint32_t)(2 * kk + hiA)) << 4) ^ swz;
            const uint32_t bk = (((uint32_t)(2 * kk + hiB)) << 4) ^ swz;
            uint32_t af[4][4];
#pragma unroll
            for (int mf = 0; mf < 4; ++mf)
                ldsm4(af[mf][0], af[mf][1], af[mf][2], af[mf][3], stA + aRow[mf] + ak);
            uint32_t bf[4][4];
#pragma unroll
            for (int nfp = 0; nfp < 4; ++nfp)
                ldsm4(bf[nfp][0], bf[nfp][1], bf[nfp][2], bf[nfp][3], stB + bRow[nfp] + bk);
#pragma unroll
            for (int mf = 0; mf < 4; ++mf)
#pragma unroll
                for (int nf = 0; nf < 8; ++nf)
                    mma_f16(acc[mf][nf], af[mf],
                            bf[nf >> 1][(nf & 1) * 2], bf[nf >> 1][(nf & 1) * 2 + 1]);
        }
    }

    const int g   = lane >> 2;
    const int tig = lane & 3;
    __half* hsm = reinterpret_cast<__half*>(smraw);
    if (MODE == 1 || MODE == 2) __syncthreads();

#pragma unroll
    for (int mf = 0; mf < 4; ++mf) {
#pragma unroll
        for (int nf = 0; nf < 8; ++nf) {
#pragma unroll
            for (int h = 0; h < 2; ++h) {
                const int rl = wm + mf * 16 + g + h * 8;
                const int cl = wn + nf * 8 + 2 * tig;
                const int r = m0 + rl;
                const int c = n0 + cl;
                const size_t idx = (size_t)r * N + c;
                float v0 = acc[mf][nf][h * 2 + 0];
                float v1 = acc[mf][nf][h * 2 + 1];
                if (EPI == 1) {
                    const float2 a1 = *reinterpret_cast<const float2*>(e1 + idx);
                    const float2 a2 = *reinterpret_cast<const float2*>(e2 + idx);
                    v0 += a1.x - a2.x;
                    v1 += a1.y - a2.y;
                } else if (EPI == 2) {
                    const float2 w  = *reinterpret_cast<const float2*>(e1 + idx);
                    const float2 lr = *reinterpret_cast<const float2*>(e2 + idx);
                    const float bi  = ev0[r];
                    v0 = w.x - lr.x * (coef * (v0 + bi * ev1[c]));
                    v1 = w.y - lr.y * (coef * (v1 + bi * ev1[c + 1]));
                } else if (EPI == 5) {
                    const __half2 qh = *reinterpret_cast<const __half2*>(e1h + idx);
                    v0 += __half2float(qh.x) + ev0[c];
                    v1 += __half2float(qh.y) + ev0[c + 1];
                }
                if (MODE == 0 || MODE == 2) {
                    float2 out; out.x = v0; out.y = v1;
                    *reinterpret_cast<float2*>(C + idx) = out;
                }
                if (MODE == 3) {
                    __half2 hp;
                    hp.x = __float2half_rn(v0);
                    hp.y = __float2half_rn(v1);
                    *reinterpret_cast<__half2*>(Ch + idx) = hp;
                }
                if (MODE == 1 || MODE == 2) {
                    hsm[(cl + 0) * 136 + rl] = __float2half_rn(v0);
                    hsm[(cl + 1) * 136 + rl] = __float2half_rn(v1);
                }
            }
        }
    }

    if (MODE == 1 || MODE == 2) {
        __syncthreads();
#pragma unroll
        for (int i = 0; i < 16; ++i) {
            const int chunk = tid + (i << 7);
            const int row  = chunk >> 4;
            const int c16  = (chunk & 15) << 3;
            const uint4 v = *reinterpret_cast<const uint4*>(hsm + row * 136 + c16);
            *reinterpret_cast<uint4*>(CTh + (size_t)(n0 + row) * M + m0 + c16) = v;
        }
    }
}

// ---------------------------------------------------------------------------
// fp16 symmetric Gram GEMM (R14 proven 4-warp config, fp32 acc).
// ---------------------------------------------------------------------------
__global__ void __launch_bounds__(128, 2)
symgemmH(const __half* __restrict__ A, __half* __restrict__ Ch, int N, int K)
{
    constexpr int BK   = 64;
    constexpr int TILE = 128 * 128;
    constexpr int SS   = 2 * TILE;

    extern __shared__ __align__(128) char smraw[];
    const uint32_t sb = (uint32_t)__cvta_generic_to_shared(smraw);

    const int tid  = threadIdx.x;
    const int lane = tid & 31;
    const int wid  = tid >> 5;
    const int wm   = (wid & 1) * 64;
    const int wn   = (wid >> 1) * 64;

    const int i = blockIdx.x;
    int e = (int)((sqrtf(8.0f * (float)i + 1.0f) - 1.0f) * 0.5f);
    while ((e + 1) * (e + 2) / 2 <= i) ++e;
    while (e * (e + 1) / 2 > i) --e;
    const int by = e;
    const int bx = i - e * (e + 1) / 2;
    const int m0 = by * 128;
    const int n0 = bx * 128;

    const int lr = tid >> 3;
    const int lc = tid & 7;
    const uint32_t lOff = (uint32_t)(lr * 128 + ((lc ^ (lr & 7)) << 4));
    const __half* aG = A + (size_t)(m0 + lr) * K + lc * 8;
    const __half* bG = A + (size_t)(n0 + lr) * K + lc * 8;

    auto loadTile = [&](int t) {
        const uint32_t base = sb + (uint32_t)((t % 3) * SS);
        const __half* a = aG + (size_t)t * BK;
        const __half* b = bG + (size_t)t * BK;
#pragma unroll
        for (int ii = 0; ii < 8; ++ii)
            cp16(base + lOff + 2048u * ii, a + (size_t)(16 * ii) * K);
#pragma unroll
        for (int ii = 0; ii < 8; ++ii)
            cp16(base + TILE + lOff + 2048u * ii, b + (size_t)(16 * ii) * K);
        asm volatile("cp.async.commit_group;" ::: "memory");
    };

    const int rr  = lane & 7;
    const int loA = (lane >> 3) & 1;
    const int hiA = (lane >> 4) & 1;
    const int loB = (lane >> 4) & 1;
    const int hiB = (lane >> 3) & 1;
    const uint32_t swz = (uint32_t)rr << 4;

    uint32_t aRow[4], bRow[4];
#pragma unroll
    for (int mf = 0; mf < 4; ++mf)
        aRow[mf] = (uint32_t)((wm + mf * 16 + loA * 8 + rr) * 128);
#pragma unroll
    for (int nfp = 0; nfp < 4; ++nfp)
        bRow[nfp] = (uint32_t)((wn + nfp * 16 + loB * 8 + rr) * 128);

    float acc[4][8][4];
#pragma unroll
    for (int a = 0; a < 4; ++a)
#pragma unroll
        for (int b = 0; b < 8; ++b)
#pragma unroll
            for (int k = 0; k < 4; ++k) acc[a][b][k] = 0.0f;

    const int nt = K / BK;
    loadTile(0);
    loadTile(1);

    for (int t = 0; t < nt; ++t) {
        if (t + 1 < nt) asm volatile("cp.async.wait_group 1;" ::: "memory");
        else            asm volatile("cp.async.wait_group 0;" ::: "memory");
        __syncthreads();
        if (t + 2 < nt) loadTile(t + 2);

        const uint32_t stA = sb + (uint32_t)((t % 3) * SS);
        const uint32_t stB = stA + TILE;

#pragma unroll
        for (int kk = 0; kk < 4; ++kk) {
            const uint32_t ak = (((uint32_t)(2 * kk + hiA)) << 4) ^ swz;
            const uint32_t bk = (((uint32_t)(2 * kk + hiB)) << 4) ^ swz;
            uint32_t af[4][4];
#pragma unroll
            for (int mf = 0; mf < 4; ++mf)
                ldsm4(af[mf][0], af[mf][1], af[mf][2], af[mf][3], stA + aRow[mf] + ak);
            uint32_t bf[4][4];
#pragma unroll
            for (int nfp = 0; nfp < 4; ++nfp)
                ldsm4(bf[nfp][0], bf[nfp][1], bf[nfp][2], bf[nfp][3], stB + bRow[nfp] + bk);
#pragma unroll
            for (int mf = 0; mf < 4; ++mf)
#pragma unroll
                for (int nf = 0; nf < 8; ++nf)
                    mma_f16(acc[mf][nf], af[mf],
                            bf[nf >> 1][(nf & 1) * 2], bf[nf >> 1][(nf & 1) * 2 + 1]);
        }
    }

    const int g   = lane >> 2;
    const int tig = lane & 3;
    __half* hsm = reinterpret_cast<__half*>(smraw);
    const bool mirror = (bx != by);
    if (mirror) __syncthreads();

#pragma unroll
    for (int mf = 0; mf < 4; ++mf) {
#pragma unroll
        for (int nf = 0; nf < 8; ++nf) {
#pragma unroll
            for (int h = 0; h < 2; ++h) {
                const int rl = wm + mf * 16 + g + h * 8;
                const int cl = wn + nf * 8 + 2 * tig;
                const __half h0 = __float2half_rn(acc[mf][nf][h * 2 + 0]);
                const __half h1 = __float2half_rn(acc[mf][nf][h * 2 + 1]);
                __half2 hp; hp.x = h0; hp.y = h1;
                *reinterpret_cast<__half2*>(Ch + (size_t)(m0 + rl) * N + n0 + cl) = hp;
                if (mirror) {
                    hsm[(cl + 0) * 136 + rl] = h0;
                    hsm[(cl + 1) * 136 + rl] = h1;
                }
            }
        }
    }

    if (mirror) {
        __syncthreads();
#pragma unroll
        for (int ii = 0; ii < 16; ++ii) {
            const int chunk = tid + (ii << 7);
            const int row  = chunk >> 4;
            const int c16  = (chunk & 15) << 3;
            const uint4 v = *reinterpret_cast<const uint4*>(hsm + row * 136 + c16);
            *reinterpret_cast<uint4*>(Ch + (size_t)(n0 + row) * N + m0 + c16) = v;
        }
    }
}

// ---------------- small kernels ----------------------------------------------
__global__ void half_kernel(const float* __restrict__ in, __half* __restrict__ out, int n)
{
    int i = blockIdx.x * blockDim.x + threadIdx.x;
    if (i < n) out[i] = __float2half_rn(in[i]);
}

__global__ void prep_dual(const float* __restrict__ in, __half* __restrict__ outRh,
                          __half* __restrict__ outTh, int R, int C)
{
    __shared__ float tile[32][33];
    const int bx = blockIdx.x * 32, by = blockIdx.y * 32;
    const int x = threadIdx.x, y = threadIdx.y;
#pragma unroll
    for (int j = 0; j < 32; j += 8) {
        const float v = in[(size_t)(by + y + j) * C + bx + x];
        tile[y + j][x] = v;
        outRh[(size_t)(by + y + j) * C + bx + x] = __float2half_rn(v);
    }
    __syncthreads();
#pragma unroll
    for (int j = 0; j < 32; j += 8)
        outTh[(size_t)(bx + y + j) * R + by + x] = __float2half_rn(tile[x][y + j]);
}

__global__ void prep_T(const float* __restrict__ in, __half* __restrict__ outTh, int R, int C)
{
    __shared__ float tile[32][33];
    const int bx = blockIdx.x * 32, by = blockIdx.y * 32;
    const int x = threadIdx.x, y = threadIdx.y;
#pragma unroll
    for (int j = 0; j < 32; j += 8)
        tile[y + j][x] = in[(size_t)(by + y + j) * C + bx + x];
    __syncthreads();
#pragma unroll
    for (int j = 0; j < 32; j += 8)
        outTh[(size_t)(bx + y + j) * R + by + x] = __float2half_rn(tile[x][y + j]);
}

__global__ void colsum_kernel(const float* __restrict__ in, float* __restrict__ part)
{
    int col = blockIdx.x * blockDim.x + threadIdx.x;
    int chunk = blockIdx.y;
    const float* p = in + (size_t)chunk * 128 * D_DIM + col;
    float s0 = 0.f, s1 = 0.f, s2 = 0.f, s3 = 0.f;
#pragma unroll
    for (int r = 0; r < 128; r += 4) {
        s0 += p[(size_t)(r + 0) * D_DIM];
        s1 += p[(size_t)(r + 1) * D_DIM];
        s2 += p[(size_t)(r + 2) * D_DIM];
        s3 += p[(size_t)(r + 3) * D_DIM];
    }
    part[chunk * D_DIM + col] = (s0 + s1) + (s2 + s3);
}

__global__ void creduce_kernel(const float* __restrict__ part, float* __restrict__ c)
{
    int j = blockIdx.x * blockDim.x + threadIdx.x;
    float s = 0.f;
#pragma unroll
    for (int ch = 0; ch < 32; ++ch) s += part[ch * D_DIM + j];
    c[j] = s;
}

__global__ void vecmat_kernel(const float* __restrict__ vec, const float* __restrict__ Mat,
                              float* __restrict__ outv)
{
    int j = blockIdx.x * blockDim.x + threadIdx.x;
    float s0 = 0.f, s1 = 0.f, s2 = 0.f, s3 = 0.f;
#pragma unroll 4
    for (int k = 0; k < D_DIM; k += 4) {
        s0 += vec[k + 0] * Mat[(size_t)(k + 0) * D_DIM + j];
        s1 += vec[k + 1] * Mat[(size_t)(k + 1) * D_DIM + j];
        s2 += vec[k + 2] * Mat[(size_t)(k + 2) * D_DIM + j];
        s3 += vec[k + 3] * Mat[(size_t)(k + 3) * D_DIM + j];
    }
    outv[j] = (s0 + s1) + (s2 + s3);
}

__global__ void bn_kernel(const float* __restrict__ Mm, const float* __restrict__ c,
                          const float* __restrict__ b, const float* __restrict__ lrb,
                          float* __restrict__ bn, float coef)
{
    int j = blockIdx.x * blockDim.x + threadIdx.x;
    float s0 = 0.f, s1 = 0.f, s2 = 0.f, s3 = 0.f;
#pragma unroll 4
    for (int k = 0; k < D_DIM; k += 4) {
        s0 += c[k + 0] * Mm[(size_t)(k + 0) * D_DIM + j];
        s1 += c[k + 1] * Mm[(size_t)(k + 1) * D_DIM + j];
        s2 += c[k + 2] * Mm[(size_t)(k + 2) * D_DIM + j];
        s3 += c[k + 3] * Mm[(size_t)(k + 3) * D_DIM + j];
    }
    float s = (s0 + s1) + (s2 + s3);
    bn[j] = b[j] - lrb[j] * coef * (s + (float)B_TOK * b[j]);
}

// ---------------- host --------------------------------------------------------
extern "C" void kernel_launch(void* const* d_in, const int* in_sizes, int n_in,
                              void* d_out, int out_size)
{
    const float* src  = (const float*)d_in[0];
    const float* th_k = (const float*)d_in[1];
    const float* th_q = (const float*)d_in[2];
    const float* th_v = (const float*)d_in[3];
    const float* W    = (const float*)d_in[4];
    const float* b    = (const float*)d_in[5];
    const float* lr_w = (const float*)d_in[6];
    const float* lr_b = (const float*)d_in[7];
    float* out = (float*)d_out;

    float *Mm, *part, *cvec, *vvec, *bn;
    __half *srcRh, *srcTh, *thkRh, *thkTh, *WRh, *thqTh, *qvh, *Sh, *MTh, *T1Th, *Wnh;
    cudaGetSymbolAddress((void**)&srcRh, g_srcRh);
    cudaGetSymbolAddress((void**)&srcTh, g_srcTh);
    cudaGetSymbolAddress((void**)&thkRh, g_thkRh);
    cudaGetSymbolAddress((void**)&thkTh, g_thkTh);
    cudaGetSymbolAddress((void**)&WRh,   g_WRh);
    cudaGetSymbolAddress((void**)&thqTh, g_thqTh);
    cudaGetSymbolAddress((void**)&qvh,   g_qvh);
    cudaGetSymbolAddress((void**)&Sh,    g_Sh);
    cudaGetSymbolAddress((void**)&Mm,    g_M);
    cudaGetSymbolAddress((void**)&MTh,   g_MTh);
    cudaGetSymbolAddress((void**)&T1Th,  g_T1Th);
    cudaGetSymbolAddress((void**)&Wnh,   g_Wnh);
    cudaGetSymbolAddress((void**)&part,  g_part);
    cudaGetSymbolAddress((void**)&cvec,  g_c);
    cudaGetSymbolAddress((void**)&vvec,  g_v);
    cudaGetSymbolAddress((void**)&bn,    g_bn);

    static cudaStream_t s2 = nullptr;
    static cudaEvent_t evSrc = nullptr, evThk = nullptr, evM = nullptr, evQv = nullptr;
    static cudaEvent_t evRoot = nullptr;
    if (s2 == nullptr) {
        cudaStreamCreateWithFlags(&s2, cudaStreamNonBlocking);
        cudaEventCreateWithFlags(&evSrc,  cudaEventDisableTiming);
        cudaEventCreateWithFlags(&evThk,  cudaEventDisableTiming);
        cudaEventCreateWithFlags(&evM,    cudaEventDisableTiming);
        cudaEventCreateWithFlags(&evQv,   cudaEventDisableTiming);
        cudaEventCreateWithFlags(&evRoot, cudaEventDisableTiming);
    }

    const float coef = 2.0f / ((float)B_TOK * (float)D_DIM);
    const int SMEM = 3 * 2 * 128 * 128;   // 98304

    cudaFuncSetAttribute(hgemm<1, 2>, cudaFuncAttributeMaxDynamicSharedMemorySize, SMEM);
    cudaFuncSetAttribute(hgemm<0, 1>, cudaFuncAttributeMaxDynamicSharedMemorySize, SMEM);
    cudaFuncSetAttribute(hgemm<0, 3>, cudaFuncAttributeMaxDynamicSharedMemorySize, SMEM);
    cudaFuncSetAttribute(hgemm<2, 3>, cudaFuncAttributeMaxDynamicSharedMemorySize, SMEM);
    cudaFuncSetAttribute(hgemm<5, 0>, cudaFuncAttributeMaxDynamicSharedMemorySize, SMEM);
    cudaFuncSetAttribute(symgemmH,    cudaFuncAttributeMaxDynamicSharedMemorySize, SMEM);

    dim3 tb(32, 8);
    dim3 gridD(D_DIM / 128, D_DIM / 128);   // 256 CTAs
    dim3 gridB(D_DIM / 128, B_TOK / 128);   // 512 CTAs
    const int nSymTiles = (D_DIM / 128) * (D_DIM / 128 + 1) / 2;   // 136

    // Root event so the fork stream is ordered after capture begin.
    cudaEventRecord(evRoot, 0);
    cudaStreamWaitEvent(s2, evRoot, 0);

    // ---- fork stream s2 (starts immediately) ----
    prep_dual<<<dim3(D_DIM / 32, D_DIM / 32), tb, 0, s2>>>(th_k, thkRh, thkTh, D_DIM, D_DIM);
    cudaEventRecord(evThk, s2);
    half_kernel<<<(D_DIM * D_DIM + 255) / 256, 256, 0, s2>>>(W, WRh, D_DIM * D_DIM);
    // M = theta_k @ W^T + theta_k - theta_v  -> Mm fp32 + MTh half
    hgemm<1, 2><<<gridD, 128, SMEM, s2>>>(thkRh, WRh, Mm, nullptr, MTh, D_DIM, D_DIM, D_DIM,
                                          th_k, th_v, nullptr, nullptr, nullptr, 0.f);
    cudaEventRecord(evM, s2);
    prep_T<<<dim3(D_DIM / 32, D_DIM / 32), tb, 0, s2>>>(th_q, thqTh, D_DIM, D_DIM);

    // ---- main stream ----
    prep_dual<<<dim3(D_DIM / 32, B_TOK / 32), tb>>>(src, srcRh, srcTh, B_TOK, D_DIM);
    cudaEventRecord(evSrc, 0);
    colsum_kernel<<<dim3(D_DIM / 256, 32), 256>>>(src, part);
    creduce_kernel<<<D_DIM / 256, 256>>>(part, cvec);
    vecmat_kernel<<<D_DIM / 128, 128>>>(cvec, th_k, vvec);
    symgemmH<<<nSymTiles, 128, SMEM>>>(srcTh, Sh, D_DIM, B_TOK);

    // fork continues: qv = src @ theta_q  (needs srcRh from main)
    cudaStreamWaitEvent(s2, evSrc, 0);
    hgemm<0, 3><<<gridB, 128, SMEM, s2>>>(srcRh, thqTh, nullptr, qvh, nullptr,
                                          B_TOK, D_DIM, D_DIM,
                                          nullptr, nullptr, nullptr, nullptr, nullptr, 0.f);
    cudaEventRecord(evQv, s2);

    // main: T1T = (S @ theta_k)^T  (needs thkTh from fork)
    cudaStreamWaitEvent(0, evThk, 0);
    hgemm<0, 1><<<gridD, 128, SMEM>>>(Sh, thkTh, nullptr, nullptr, T1Th, D_DIM, D_DIM, D_DIM,
                                      nullptr, nullptr, nullptr, nullptr, nullptr, 0.f);

    // Wn needs M only (not qv)
    cudaStreamWaitEvent(0, evM, 0);
    bn_kernel<<<D_DIM / 128, 128>>>(Mm, cvec, b, lr_b, bn, coef);

    // Wnh = half( W - lr_w * coef * (M^T @ T1 + b (x) v) )
    hgemm<2, 3><<<gridD, 128, SMEM>>>(MTh, T1Th, nullptr, Wnh, nullptr, D_DIM, D_DIM, D_DIM,
                                      W, lr_w, b, vvec, nullptr, coef);

    // z = qv @ Wn^T + qv + bn  (needs qv)
    cudaStreamWaitEvent(0, evQv, 0);
    hgemm<5, 0><<<gridB, 128, SMEM>>>(qvh, Wnh, out, nullptr, nullptr, B_TOK, D_DIM, D_DIM,
                                      nullptr, nullptr, bn, nullptr, qvh, 0.f);
}

// round 17
// speedup vs baseline: 1.2646x; 1.1870x over previous
#include <cuda_runtime.h>
#include <cuda_fp16.h>
#include <cstdint>
#include <math.h>

#define D_DIM 2048
#define B_TOK 4096

// ---------------- scratch (device globals; no allocation allowed) ----------
__device__ __half g_srcRh[(size_t)B_TOK * D_DIM];
__device__ __half g_srcTh[(size_t)B_TOK * D_DIM];
__device__ __half g_thkRh[(size_t)D_DIM * D_DIM];
__device__ __half g_thkTh[(size_t)D_DIM * D_DIM];
__device__ __half g_WRh [(size_t)D_DIM * D_DIM];
__device__ __half g_thqTh[(size_t)D_DIM * D_DIM];
__device__ __half g_qvh [(size_t)B_TOK * D_DIM];
__device__ __half g_Sh  [(size_t)D_DIM * D_DIM];
__device__ float  g_M   [(size_t)D_DIM * D_DIM];
__device__ __half g_MTh [(size_t)D_DIM * D_DIM];
__device__ __half g_T1Th[(size_t)D_DIM * D_DIM];
__device__ __half g_Wnh [(size_t)D_DIM * D_DIM];
__device__ float  g_part[32 * D_DIM];
__device__ float  g_c   [D_DIM];
__device__ float  g_v   [D_DIM];
__device__ float  g_bn  [D_DIM];

// ---------------- PTX helpers ----------------------------------------------
__device__ __forceinline__ void cp16(uint32_t dst, const void* src) {
    asm volatile("cp.async.cg.shared.global [%0], [%1], 16;" :: "r"(dst), "l"(src));
}

__device__ __forceinline__ void ldsm4(uint32_t& r0, uint32_t& r1, uint32_t& r2, uint32_t& r3,
                                      uint32_t addr) {
    asm volatile("ldmatrix.sync.aligned.m8n8.x4.shared.b16 {%0,%1,%2,%3}, [%4];"
                 : "=r"(r0), "=r"(r1), "=r"(r2), "=r"(r3) : "r"(addr));
}

__device__ __forceinline__ void mma_f16(float c[4], const uint32_t a[4],
                                        uint32_t b0, uint32_t b1) {
    asm volatile(
        "mma.sync.aligned.m16n8k16.row.col.f32.f16.f16.f32 "
        "{%0,%1,%2,%3}, {%4,%5,%6,%7}, {%8,%9}, {%0,%1,%2,%3};"
        : "+f"(c[0]), "+f"(c[1]), "+f"(c[2]), "+f"(c[3])
        : "r"(a[0]), "r"(a[1]), "r"(a[2]), "r"(a[3]), "r"(b0), "r"(b1));
}

// ---------------------------------------------------------------------------
// fp16 4-warp NT GEMM (R12/R14 proven): C[M,N] = A[M,K]*B[N,K]^T, fp32 acc.
// CTA 128x128, 4 warps of 64x64, BK=64 halves, 3-stage, launch_bounds(128,2).
// mBase/nBase: tile-origin offsets (for split launches).
// EPI 0: v = acc
// EPI 1: v = acc + e1[idx] - e2[idx]
// EPI 2: v = e1[idx] - e2[idx]*coef*(acc + ev0[r]*ev1[c])
// EPI 5: v = acc + half(e1h[idx]) + ev0[col]
// MODE 0: fp32 C.  MODE 1: half CT only.  MODE 2: fp32 C + half CT.
// MODE 3: half Ch (non-transposed).
// ---------------------------------------------------------------------------
template <int EPI, int MODE>
__global__ void __launch_bounds__(128, 2)
hgemm(const __half* __restrict__ A, const __half* __restrict__ B,
      float* __restrict__ C, __half* __restrict__ Ch, __half* __restrict__ CTh,
      int M, int N, int K, int mBase, int nBase,
      const float* __restrict__ e1, const float* __restrict__ e2,
      const float* __restrict__ ev0, const float* __restrict__ ev1,
      const __half* __restrict__ e1h, float coef)
{
    constexpr int BK   = 64;             // halves
    constexpr int TILE = 128 * 128;      // bytes
    constexpr int SS   = 2 * TILE;

    extern __shared__ __align__(128) char smraw[];
    const uint32_t sb = (uint32_t)__cvta_generic_to_shared(smraw);

    const int tid  = threadIdx.x;
    const int lane = tid & 31;
    const int wid  = tid >> 5;
    const int wm   = (wid & 1) * 64;
    const int wn   = (wid >> 1) * 64;
    const int m0   = mBase + blockIdx.y * 128;
    const int n0   = nBase + blockIdx.x * 128;

    const int lr = tid >> 3;
    const int lc = tid & 7;
    const uint32_t lOff = (uint32_t)(lr * 128 + ((lc ^ (lr & 7)) << 4));
    const __half* aG = A + (size_t)(m0 + lr) * K + lc * 8;
    const __half* bG = B + (size_t)(n0 + lr) * K + lc * 8;

    auto loadTile = [&](int t) {
        const uint32_t base = sb + (uint32_t)((t % 3) * SS);
        const __half* a = aG + (size_t)t * BK;
        const __half* b = bG + (size_t)t * BK;
#pragma unroll
        for (int i = 0; i < 8; ++i)
            cp16(base + lOff + 2048u * i, a + (size_t)(16 * i) * K);
#pragma unroll
        for (int i = 0; i < 8; ++i)
            cp16(base + TILE + lOff + 2048u * i, b + (size_t)(16 * i) * K);
        asm volatile("cp.async.commit_group;" ::: "memory");
    };

    const int rr  = lane & 7;
    const int loA = (lane >> 3) & 1;
    const int hiA = (lane >> 4) & 1;
    const int loB = (lane >> 4) & 1;
    const int hiB = (lane >> 3) & 1;
    const uint32_t swz = (uint32_t)rr << 4;

    uint32_t aRow[4], bRow[4];
#pragma unroll
    for (int mf = 0; mf < 4; ++mf)
        aRow[mf] = (uint32_t)((wm + mf * 16 + loA * 8 + rr) * 128);
#pragma unroll
    for (int nfp = 0; nfp < 4; ++nfp)
        bRow[nfp] = (uint32_t)((wn + nfp * 16 + loB * 8 + rr) * 128);

    float acc[4][8][4];
#pragma unroll
    for (int i = 0; i < 4; ++i)
#pragma unroll
        for (int j = 0; j < 8; ++j)
#pragma unroll
            for (int k = 0; k < 4; ++k) acc[i][j][k] = 0.0f;

    const int nt = K / BK;
    loadTile(0);
    loadTile(1);

    for (int t = 0; t < nt; ++t) {
        if (t + 1 < nt) asm volatile("cp.async.wait_group 1;" ::: "memory");
        else            asm volatile("cp.async.wait_group 0;" ::: "memory");
        __syncthreads();
        if (t + 2 < nt) loadTile(t + 2);

        const uint32_t stA = sb + (uint32_t)((t % 3) * SS);
        const uint32_t stB = stA + TILE;

#pragma unroll
        for (int kk = 0; kk < 4; ++kk) {
            const uint32_t ak = (((uint32_t)(2 * kk + hiA)) << 4) ^ swz;
            const uint32_t bk = (((uint32_t)(2 * kk + hiB)) << 4) ^ swz;
            uint32_t af[4][4];
#pragma unroll
            for (int mf = 0; mf < 4; ++mf)
                ldsm4(af[mf][0], af[mf][1], af[mf][2], af[mf][3], stA + aRow[mf] + ak);
            uint32_t bf[4][4];
#pragma unroll
            for (int nfp = 0; nfp < 4; ++nfp)
                ldsm4(bf[nfp][0], bf[nfp][1], bf[nfp][2], bf[nfp][3], stB + bRow[nfp] + bk);
#pragma unroll
            for (int mf = 0; mf < 4; ++mf)
#pragma unroll
                for (int nf = 0; nf < 8; ++nf)
                    mma_f16(acc[mf][nf], af[mf],
                            bf[nf >> 1][(nf & 1) * 2], bf[nf >> 1][(nf & 1) * 2 + 1]);
        }
    }

    const int g   = lane >> 2;
    const int tig = lane & 3;
    __half* hsm = reinterpret_cast<__half*>(smraw);
    if (MODE == 1 || MODE == 2) __syncthreads();

#pragma unroll
    for (int mf = 0; mf < 4; ++mf) {
#pragma unroll
        for (int nf = 0; nf < 8; ++nf) {
#pragma unroll
            for (int h = 0; h < 2; ++h) {
                const int rl = wm + mf * 16 + g + h * 8;
                const int cl = wn + nf * 8 + 2 * tig;
                const int r = m0 + rl;
                const int c = n0 + cl;
                const size_t idx = (size_t)r * N + c;
                float v0 = acc[mf][nf][h * 2 + 0];
                float v1 = acc[mf][nf][h * 2 + 1];
                if (EPI == 1) {
                    const float2 a1 = *reinterpret_cast<const float2*>(e1 + idx);
                    const float2 a2 = *reinterpret_cast<const float2*>(e2 + idx);
                    v0 += a1.x - a2.x;
                    v1 += a1.y - a2.y;
                } else if (EPI == 2) {
                    const float2 w  = *reinterpret_cast<const float2*>(e1 + idx);
                    const float2 lr = *reinterpret_cast<const float2*>(e2 + idx);
                    const float bi  = ev0[r];
                    v0 = w.x - lr.x * (coef * (v0 + bi * ev1[c]));
                    v1 = w.y - lr.y * (coef * (v1 + bi * ev1[c + 1]));
                } else if (EPI == 5) {
                    const __half2 qh = *reinterpret_cast<const __half2*>(e1h + idx);
                    v0 += __half2float(qh.x) + ev0[c];
                    v1 += __half2float(qh.y) + ev0[c + 1];
                }
                if (MODE == 0 || MODE == 2) {
                    float2 out; out.x = v0; out.y = v1;
                    *reinterpret_cast<float2*>(C + idx) = out;
                }
                if (MODE == 3) {
                    __half2 hp;
                    hp.x = __float2half_rn(v0);
                    hp.y = __float2half_rn(v1);
                    *reinterpret_cast<__half2*>(Ch + idx) = hp;
                }
                if (MODE == 1 || MODE == 2) {
                    hsm[(cl + 0) * 136 + rl] = __float2half_rn(v0);
                    hsm[(cl + 1) * 136 + rl] = __float2half_rn(v1);
                }
            }
        }
    }

    if (MODE == 1 || MODE == 2) {
        __syncthreads();
#pragma unroll
        for (int i = 0; i < 16; ++i) {
            const int chunk = tid + (i << 7);
            const int row  = chunk >> 4;
            const int c16  = (chunk & 15) << 3;
            const uint4 v = *reinterpret_cast<const uint4*>(hsm + row * 136 + c16);
            *reinterpret_cast<uint4*>(CTh + (size_t)(n0 + row) * M + m0 + c16) = v;
        }
    }
}

// ---------------------------------------------------------------------------
// fp16 symmetric Gram GEMM (R14 proven 4-warp config, fp32 acc).
// ---------------------------------------------------------------------------
__global__ void __launch_bounds__(128, 2)
symgemmH(const __half* __restrict__ A, __half* __restrict__ Ch, int N, int K)
{
    constexpr int BK   = 64;
    constexpr int TILE = 128 * 128;
    constexpr int SS   = 2 * TILE;

    extern __shared__ __align__(128) char smraw[];
    const uint32_t sb = (uint32_t)__cvta_generic_to_shared(smraw);

    const int tid  = threadIdx.x;
    const int lane = tid & 31;
    const int wid  = tid >> 5;
    const int wm   = (wid & 1) * 64;
    const int wn   = (wid >> 1) * 64;

    const int i = blockIdx.x;
    int e = (int)((sqrtf(8.0f * (float)i + 1.0f) - 1.0f) * 0.5f);
    while ((e + 1) * (e + 2) / 2 <= i) ++e;
    while (e * (e + 1) / 2 > i) --e;
    const int by = e;
    const int bx = i - e * (e + 1) / 2;
    const int m0 = by * 128;
    const int n0 = bx * 128;

    const int lr = tid >> 3;
    const int lc = tid & 7;
    const uint32_t lOff = (uint32_t)(lr * 128 + ((lc ^ (lr & 7)) << 4));
    const __half* aG = A + (size_t)(m0 + lr) * K + lc * 8;
    const __half* bG = A + (size_t)(n0 + lr) * K + lc * 8;

    auto loadTile = [&](int t) {
        const uint32_t base = sb + (uint32_t)((t % 3) * SS);
        const __half* a = aG + (size_t)t * BK;
        const __half* b = bG + (size_t)t * BK;
#pragma unroll
        for (int ii = 0; ii < 8; ++ii)
            cp16(base + lOff + 2048u * ii, a + (size_t)(16 * ii) * K);
#pragma unroll
        for (int ii = 0; ii < 8; ++ii)
            cp16(base + TILE + lOff + 2048u * ii, b + (size_t)(16 * ii) * K);
        asm volatile("cp.async.commit_group;" ::: "memory");
    };

    const int rr  = lane & 7;
    const int loA = (lane >> 3) & 1;
    const int hiA = (lane >> 4) & 1;
    const int loB = (lane >> 4) & 1;
    const int hiB = (lane >> 3) & 1;
    const uint32_t swz = (uint32_t)rr << 4;

    uint32_t aRow[4], bRow[4];
#pragma unroll
    for (int mf = 0; mf < 4; ++mf)
        aRow[mf] = (uint32_t)((wm + mf * 16 + loA * 8 + rr) * 128);
#pragma unroll
    for (int nfp = 0; nfp < 4; ++nfp)
        bRow[nfp] = (uint32_t)((wn + nfp * 16 + loB * 8 + rr) * 128);

    float acc[4][8][4];
#pragma unroll
    for (int a = 0; a < 4; ++a)
#pragma unroll
        for (int b = 0; b < 8; ++b)
#pragma unroll
            for (int k = 0; k < 4; ++k) acc[a][b][k] = 0.0f;

    const int nt = K / BK;
    loadTile(0);
    loadTile(1);

    for (int t = 0; t < nt; ++t) {
        if (t + 1 < nt) asm volatile("cp.async.wait_group 1;" ::: "memory");
        else            asm volatile("cp.async.wait_group 0;" ::: "memory");
        __syncthreads();
        if (t + 2 < nt) loadTile(t + 2);

        const uint32_t stA = sb + (uint32_t)((t % 3) * SS);
        const uint32_t stB = stA + TILE;

#pragma unroll
        for (int kk = 0; kk < 4; ++kk) {
            const uint32_t ak = (((uint32_t)(2 * kk + hiA)) << 4) ^ swz;
            const uint32_t bk = (((uint32_t)(2 * kk + hiB)) << 4) ^ swz;
            uint32_t af[4][4];
#pragma unroll
            for (int mf = 0; mf < 4; ++mf)
                ldsm4(af[mf][0], af[mf][1], af[mf][2], af[mf][3], stA + aRow[mf] + ak);
            uint32_t bf[4][4];
#pragma unroll
            for (int nfp = 0; nfp < 4; ++nfp)
                ldsm4(bf[nfp][0], bf[nfp][1], bf[nfp][2], bf[nfp][3], stB + bRow[nfp] + bk);
#pragma unroll
            for (int mf = 0; mf < 4; ++mf)
#pragma unroll
                for (int nf = 0; nf < 8; ++nf)
                    mma_f16(acc[mf][nf], af[mf],
                            bf[nf >> 1][(nf & 1) * 2], bf[nf >> 1][(nf & 1) * 2 + 1]);
        }
    }

    const int g   = lane >> 2;
    const int tig = lane & 3;
    __half* hsm = reinterpret_cast<__half*>(smraw);
    const bool mirror = (bx != by);
    if (mirror) __syncthreads();

#pragma unroll
    for (int mf = 0; mf < 4; ++mf) {
#pragma unroll
        for (int nf = 0; nf < 8; ++nf) {
#pragma unroll
            for (int h = 0; h < 2; ++h) {
                const int rl = wm + mf * 16 + g + h * 8;
                const int cl = wn + nf * 8 + 2 * tig;
                const __half h0 = __float2half_rn(acc[mf][nf][h * 2 + 0]);
                const __half h1 = __float2half_rn(acc[mf][nf][h * 2 + 1]);
                __half2 hp; hp.x = h0; hp.y = h1;
                *reinterpret_cast<__half2*>(Ch + (size_t)(m0 + rl) * N + n0 + cl) = hp;
                if (mirror) {
                    hsm[(cl + 0) * 136 + rl] = h0;
                    hsm[(cl + 1) * 136 + rl] = h1;
                }
            }
        }
    }

    if (mirror) {
        __syncthreads();
#pragma unroll
        for (int ii = 0; ii < 16; ++ii) {
            const int chunk = tid + (ii << 7);
            const int row  = chunk >> 4;
            const int c16  = (chunk & 15) << 3;
            const uint4 v = *reinterpret_cast<const uint4*>(hsm + row * 136 + c16);
            *reinterpret_cast<uint4*>(Ch + (size_t)(n0 + row) * N + m0 + c16) = v;
        }
    }
}

// ---------------- small kernels ----------------------------------------------
__global__ void half_kernel(const float* __restrict__ in, __half* __restrict__ out, int n)
{
    int i = blockIdx.x * blockDim.x + threadIdx.x;
    if (i < n) out[i] = __float2half_rn(in[i]);
}

__global__ void prep_dual(const float* __restrict__ in, __half* __restrict__ outRh,
                          __half* __restrict__ outTh, int R, int C)
{
    __shared__ float tile[32][33];
    const int bx = blockIdx.x * 32, by = blockIdx.y * 32;
    const int x = threadIdx.x, y = threadIdx.y;
#pragma unroll
    for (int j = 0; j < 32; j += 8) {
        const float v = in[(size_t)(by + y + j) * C + bx + x];
        tile[y + j][x] = v;
        outRh[(size_t)(by + y + j) * C + bx + x] = __float2half_rn(v);
    }
    __syncthreads();
#pragma unroll
    for (int j = 0; j < 32; j += 8)
        outTh[(size_t)(bx + y + j) * R + by + x] = __float2half_rn(tile[x][y + j]);
}

__global__ void prep_T(const float* __restrict__ in, __half* __restrict__ outTh, int R, int C)
{
    __shared__ float tile[32][33];
    const int bx = blockIdx.x * 32, by = blockIdx.y * 32;
    const int x = threadIdx.x, y = threadIdx.y;
#pragma unroll
    for (int j = 0; j < 32; j += 8)
        tile[y + j][x] = in[(size_t)(by + y + j) * C + bx + x];
    __syncthreads();
#pragma unroll
    for (int j = 0; j < 32; j += 8)
        outTh[(size_t)(bx + y + j) * R + by + x] = __float2half_rn(tile[x][y + j]);
}

__global__ void colsum_kernel(const float* __restrict__ in, float* __restrict__ part)
{
    int col = blockIdx.x * blockDim.x + threadIdx.x;
    int chunk = blockIdx.y;
    const float* p = in + (size_t)chunk * 128 * D_DIM + col;
    float s0 = 0.f, s1 = 0.f, s2 = 0.f, s3 = 0.f;
#pragma unroll
    for (int r = 0; r < 128; r += 4) {
        s0 += p[(size_t)(r + 0) * D_DIM];
        s1 += p[(size_t)(r + 1) * D_DIM];
        s2 += p[(size_t)(r + 2) * D_DIM];
        s3 += p[(size_t)(r + 3) * D_DIM];
    }
    part[chunk * D_DIM + col] = (s0 + s1) + (s2 + s3);
}

__global__ void creduce_kernel(const float* __restrict__ part, float* __restrict__ c)
{
    int j = blockIdx.x * blockDim.x + threadIdx.x;
    float s = 0.f;
#pragma unroll
    for (int ch = 0; ch < 32; ++ch) s += part[ch * D_DIM + j];
    c[j] = s;
}

__global__ void vecmat_kernel(const float* __restrict__ vec, const float* __restrict__ Mat,
                              float* __restrict__ outv)
{
    int j = blockIdx.x * blockDim.x + threadIdx.x;
    float s0 = 0.f, s1 = 0.f, s2 = 0.f, s3 = 0.f;
#pragma unroll 4
    for (int k = 0; k < D_DIM; k += 4) {
        s0 += vec[k + 0] * Mat[(size_t)(k + 0) * D_DIM + j];
        s1 += vec[k + 1] * Mat[(size_t)(k + 1) * D_DIM + j];
        s2 += vec[k + 2] * Mat[(size_t)(k + 2) * D_DIM + j];
        s3 += vec[k + 3] * Mat[(size_t)(k + 3) * D_DIM + j];
    }
    outv[j] = (s0 + s1) + (s2 + s3);
}

__global__ void bn_kernel(const float* __restrict__ Mm, const float* __restrict__ c,
                          const float* __restrict__ b, const float* __restrict__ lrb,
                          float* __restrict__ bn, float coef)
{
    int j = blockIdx.x * blockDim.x + threadIdx.x;
    float s0 = 0.f, s1 = 0.f, s2 = 0.f, s3 = 0.f;
#pragma unroll 4
    for (int k = 0; k < D_DIM; k += 4) {
        s0 += c[k + 0] * Mm[(size_t)(k + 0) * D_DIM + j];
        s1 += c[k + 1] * Mm[(size_t)(k + 1) * D_DIM + j];
        s2 += c[k + 2] * Mm[(size_t)(k + 2) * D_DIM + j];
        s3 += c[k + 3] * Mm[(size_t)(k + 3) * D_DIM + j];
    }
    float s = (s0 + s1) + (s2 + s3);
    bn[j] = b[j] - lrb[j] * coef * (s + (float)B_TOK * b[j]);
}

// ---------------- host --------------------------------------------------------
extern "C" void kernel_launch(void* const* d_in, const int* in_sizes, int n_in,
                              void* d_out, int out_size)
{
    const float* src  = (const float*)d_in[0];
    const float* th_k = (const float*)d_in[1];
    const float* th_q = (const float*)d_in[2];
    const float* th_v = (const float*)d_in[3];
    const float* W    = (const float*)d_in[4];
    const float* b    = (const float*)d_in[5];
    const float* lr_w = (const float*)d_in[6];
    const float* lr_b = (const float*)d_in[7];
    float* out = (float*)d_out;

    float *Mm, *part, *cvec, *vvec, *bn;
    __half *srcRh, *srcTh, *thkRh, *thkTh, *WRh, *thqTh, *qvh, *Sh, *MTh, *T1Th, *Wnh;
    cudaGetSymbolAddress((void**)&srcRh, g_srcRh);
    cudaGetSymbolAddress((void**)&srcTh, g_srcTh);
    cudaGetSymbolAddress((void**)&thkRh, g_thkRh);
    cudaGetSymbolAddress((void**)&thkTh, g_thkTh);
    cudaGetSymbolAddress((void**)&WRh,   g_WRh);
    cudaGetSymbolAddress((void**)&thqTh, g_thqTh);
    cudaGetSymbolAddress((void**)&qvh,   g_qvh);
    cudaGetSymbolAddress((void**)&Sh,    g_Sh);
    cudaGetSymbolAddress((void**)&Mm,    g_M);
    cudaGetSymbolAddress((void**)&MTh,   g_MTh);
    cudaGetSymbolAddress((void**)&T1Th,  g_T1Th);
    cudaGetSymbolAddress((void**)&Wnh,   g_Wnh);
    cudaGetSymbolAddress((void**)&part,  g_part);
    cudaGetSymbolAddress((void**)&cvec,  g_c);
    cudaGetSymbolAddress((void**)&vvec,  g_v);
    cudaGetSymbolAddress((void**)&bn,    g_bn);

    static cudaStream_t s2 = nullptr, s3 = nullptr;
    static cudaEvent_t evRoot = nullptr, evSrc = nullptr, evJoin = nullptr, evV = nullptr;
    static cudaEvent_t evW1 = nullptr, evW2 = nullptr, evZ = nullptr;
    if (s2 == nullptr) {
        cudaStreamCreateWithFlags(&s2, cudaStreamNonBlocking);
        cudaStreamCreateWithFlags(&s3, cudaStreamNonBlocking);
        cudaEventCreateWithFlags(&evRoot, cudaEventDisableTiming);
        cudaEventCreateWithFlags(&evSrc,  cudaEventDisableTiming);
        cudaEventCreateWithFlags(&evJoin, cudaEventDisableTiming);
        cudaEventCreateWithFlags(&evV,    cudaEventDisableTiming);
        cudaEventCreateWithFlags(&evW1,   cudaEventDisableTiming);
        cudaEventCreateWithFlags(&evW2,   cudaEventDisableTiming);
        cudaEventCreateWithFlags(&evZ,    cudaEventDisableTiming);
    }

    const float coef = 2.0f / ((float)B_TOK * (float)D_DIM);
    const int SMEM = 3 * 2 * 128 * 128;   // 98304

    cudaFuncSetAttribute(hgemm<1, 2>, cudaFuncAttributeMaxDynamicSharedMemorySize, SMEM);
    cudaFuncSetAttribute(hgemm<0, 1>, cudaFuncAttributeMaxDynamicSharedMemorySize, SMEM);
    cudaFuncSetAttribute(hgemm<0, 3>, cudaFuncAttributeMaxDynamicSharedMemorySize, SMEM);
    cudaFuncSetAttribute(hgemm<2, 3>, cudaFuncAttributeMaxDynamicSharedMemorySize, SMEM);
    cudaFuncSetAttribute(hgemm<5, 0>, cudaFuncAttributeMaxDynamicSharedMemorySize, SMEM);
    cudaFuncSetAttribute(symgemmH,    cudaFuncAttributeMaxDynamicSharedMemorySize, SMEM);

    dim3 tb(32, 8);
    dim3 gridD(D_DIM / 128, D_DIM / 128);       // 256 CTAs
    dim3 gridDH(D_DIM / 128, D_DIM / 256);      // 128 CTAs (half rows)
    dim3 gridB(D_DIM / 128, B_TOK / 128);       // 512 CTAs
    dim3 gridBH(D_DIM / 256, B_TOK / 128);      // 256 CTAs (half cols)
    const int nSymTiles = (D_DIM / 128) * (D_DIM / 128 + 1) / 2;   // 136

    cudaEventRecord(evRoot, 0);
    cudaStreamWaitEvent(s2, evRoot, 0);
    cudaStreamWaitEvent(s3, evRoot, 0);

    // ---- s3: reduction chain for bn (off critical path) ----
    colsum_kernel<<<dim3(D_DIM / 256, 32), 256, 0, s3>>>(src, part);
    creduce_kernel<<<D_DIM / 256, 256, 0, s3>>>(part, cvec);
    vecmat_kernel<<<D_DIM / 128, 128, 0, s3>>>(cvec, th_k, vvec);
    cudaEventRecord(evV, s3);

    // ---- main: src prep + Gram chain ----
    prep_dual<<<dim3(D_DIM / 32, B_TOK / 32), tb>>>(src, srcRh, srcTh, B_TOK, D_DIM);
    cudaEventRecord(evSrc, 0);
    prep_dual<<<dim3(D_DIM / 32, D_DIM / 32), tb>>>(th_k, thkRh, thkTh, D_DIM, D_DIM);

    // ---- s2: W half, M-GEMM, theta_q^T, qv (R14 fork content) ----
    cudaStreamWaitEvent(s2, evSrc, 0);   // also orders thk prep? no — thk prep on main below fork
    half_kernel<<<(D_DIM * D_DIM + 255) / 256, 256, 0, s2>>>(W, WRh, D_DIM * D_DIM);
    prep_T<<<dim3(D_DIM / 32, D_DIM / 32), tb, 0, s2>>>(th_q, thqTh, D_DIM, D_DIM);
    // qv = src @ theta_q (needs srcRh; evSrc already waited)
    hgemm<0, 3><<<gridB, 128, SMEM, s2>>>(srcRh, thqTh, nullptr, qvh, nullptr,
                                          B_TOK, D_DIM, D_DIM, 0, 0,
                                          nullptr, nullptr, nullptr, nullptr, nullptr, 0.f);
    cudaEventRecord(evJoin, s2);

    // ---- main: M, sym, T1 ----
    // M = theta_k @ W^T + theta_k - theta_v  (needs thkRh [main] and WRh [s2])
    symgemmH<<<nSymTiles, 128, SMEM>>>(srcTh, Sh, D_DIM, B_TOK);
    cudaStreamWaitEvent(0, evJoin, 0);   // WRh+qv done; M after (overlap note: M waits qv too — acceptable, qv overlaps sym)
    hgemm<1, 2><<<gridD, 128, SMEM>>>(thkRh, WRh, Mm, nullptr, MTh, D_DIM, D_DIM, D_DIM, 0, 0,
                                      th_k, th_v, nullptr, nullptr, nullptr, 0.f);
    // T1T = (S @ theta_k)^T
    hgemm<0, 1><<<gridD, 128, SMEM>>>(Sh, thkTh, nullptr, nullptr, T1Th, D_DIM, D_DIM, D_DIM, 0, 0,
                                      nullptr, nullptr, nullptr, nullptr, nullptr, 0.f);

    cudaStreamWaitEvent(0, evV, 0);
    bn_kernel<<<D_DIM / 128, 128>>>(Mm, cvec, b, lr_b, bn, coef);

    // Wn in two row-halves; z-half starts as soon as its Wn rows exist.
    hgemm<2, 3><<<gridDH, 128, SMEM>>>(MTh, T1Th, nullptr, Wnh, nullptr, D_DIM, D_DIM, D_DIM,
                                       0, 0, W, lr_w, b, vvec, nullptr, coef);
    cudaEventRecord(evW1, 0);
    hgemm<2, 3><<<gridDH, 128, SMEM>>>(MTh, T1Th, nullptr, Wnh, nullptr, D_DIM, D_DIM, D_DIM,
                                       1024, 0, W, lr_w, b, vvec, nullptr, coef);
    cudaEventRecord(evW2, 0);

    // z halves on s2 (qv lives there; bn precedes evW1 on main)
    cudaStreamWaitEvent(s2, evW1, 0);
    hgemm<5, 0><<<gridBH, 128, SMEM, s2>>>(qvh, Wnh, out, nullptr, nullptr,
                                           B_TOK, D_DIM, D_DIM, 0, 0,
                                           nullptr, nullptr, bn, nullptr, qvh, 0.f);
    cudaStreamWaitEvent(s2, evW2, 0);
    hgemm<5, 0><<<gridBH, 128, SMEM, s2>>>(qvh, Wnh, out, nullptr, nullptr,
                                           B_TOK, D_DIM, D_DIM, 0, 1024,
                                           nullptr, nullptr, bn, nullptr, qvh, 0.f);
    cudaEventRecord(evZ, s2);

    // join everything back to the capture stream
    cudaStreamWaitEvent(0, evZ, 0);
}